// round 11
// baseline (speedup 1.0000x reference)
#include <cuda_runtime.h>
#include <cstdint>

#define DD 1024
#define BATCH 64
#define TT 200
#define TB (TT*BATCH)

// ---------------- scratch (static __device__, no allocations) ----------------
__device__ float g_xT[TB*DD];     // x transposed to [t][b][k]
__device__ float g_WX[TB*DD];     // wx for all timesteps
__device__ float g_H [TB*DD];     // h_t for all timesteps
__device__ float g_Y [TB*DD];     // y before final transpose
__device__ float g_hph0[BATCH*DD];
__device__ float g_h   [BATCH*DD];
__device__ float g_h0  [BATCH*DD];
__device__ float g_F1  [BATCH*DD];
__device__ float g_T2  [BATCH*DD];
__device__ unsigned g_bar_count;
__device__ volatile unsigned g_bar_gen;

// ---------------- helpers ----------------
__device__ __forceinline__ void ffma2(unsigned long long& d,
                                      unsigned long long a,
                                      unsigned long long b) {
    asm("fma.rn.f32x2 %0, %1, %2, %0;" : "+l"(d) : "l"(a), "l"(b));
}
__device__ __forceinline__ float hsum2(unsigned long long v) {
    float lo = __uint_as_float((unsigned)(v & 0xffffffffu));
    float hi = __uint_as_float((unsigned)(v >> 32));
    return lo + hi;
}
__device__ __forceinline__ float elu_f(float x) {
    return x > 0.f ? x : expm1f(x);
}

__device__ __forceinline__ void grid_sync() {
    __syncthreads();
    if (threadIdx.x == 0) {
        unsigned gen = g_bar_gen;
        __threadfence();
        if (atomicAdd(&g_bar_count, 1) == gridDim.x - 1) {
            g_bar_count = 0;
            __threadfence();
            g_bar_gen = gen + 1;
        } else {
            while (g_bar_gen == gen) { __nanosleep(32); }
            __threadfence();
        }
    }
    __syncthreads();
}

// ---------------- core 16x32 tile GEMM (K=1024, warp K-split) ----------------
// O[m][n] = sum_k A[m][k] * W[n][k]; per-warp partials -> pbuf[8][512].
// ACG=true -> A read with ld.global.cg (cross-SM freshly-written data).
template<bool ACG>
__device__ __noinline__ void mm_tile(const float* __restrict__ Abase,
                                     const float* __restrict__ Wbase,
                                     float* __restrict__ pbuf)
{
    const int tid  = threadIdx.x;
    const int warp = tid >> 5;          // 0..7  -> K slice of 128
    const int lane = tid & 31;
    const int ml   = lane >> 3;         // 0..3  -> 4 m-rows each
    const int nl   = lane & 7;          // 0..7  -> 4 n-cols each
    const float* Arow = Abase + (ml*4)*DD + warp*128;
    const float* Wrow = Wbase + (nl*4)*DD + warp*128;

    unsigned long long acc[4][4];
    #pragma unroll
    for (int i = 0; i < 4; i++)
        #pragma unroll
        for (int j = 0; j < 4; j++) acc[i][j] = 0ull;

    ulonglong2 a_c[4], w_c[4];
    #pragma unroll
    for (int i = 0; i < 4; i++) {
        a_c[i] = ACG ? __ldcg((const ulonglong2*)(Arow + i*DD))
                     : __ldg ((const ulonglong2*)(Arow + i*DD));
        w_c[i] = __ldg((const ulonglong2*)(Wrow + i*DD));
    }
    #pragma unroll
    for (int c = 0; c < 32; c++) {          // 32 chunks of 4 k
        ulonglong2 a_n[4], w_n[4];
        if (c < 31) {
            #pragma unroll
            for (int i = 0; i < 4; i++) {
                a_n[i] = ACG ? __ldcg((const ulonglong2*)(Arow + i*DD + (c+1)*4))
                             : __ldg ((const ulonglong2*)(Arow + i*DD + (c+1)*4));
                w_n[i] = __ldg((const ulonglong2*)(Wrow + i*DD + (c+1)*4));
            }
        }
        #pragma unroll
        for (int i = 0; i < 4; i++)
            #pragma unroll
            for (int j = 0; j < 4; j++) {
                ffma2(acc[i][j], a_c[i].x, w_c[j].x);
                ffma2(acc[i][j], a_c[i].y, w_c[j].y);
            }
        if (c < 31) {
            #pragma unroll
            for (int i = 0; i < 4; i++) { a_c[i] = a_n[i]; w_c[i] = w_n[i]; }
        }
    }
    #pragma unroll
    for (int i = 0; i < 4; i++)
        #pragma unroll
        for (int j = 0; j < 4; j++)
            pbuf[warp*512 + (ml*4 + i)*32 + nl*4 + j] = hsum2(acc[i][j]);
}

// ---------------- persistent sequential kernel ----------------
__global__ void __launch_bounds__(256, 1) ernn_seq(
    const float* __restrict__ Whid, const float* __restrict__ bhid,
    const float* __restrict__ W2,   const float* __restrict__ b2,
    const float* __restrict__ W3,   const float* __restrict__ b3,
    const float* __restrict__ etas)
{
    __shared__ float pbuf[8*512];
    const int tid   = threadIdx.x;
    const int mg    = blockIdx.x >> 5;     // 0..3   (16 rows each)
    const int ng    = blockIdx.x & 31;     // 0..31  (32 cols each)
    const int mbase = mg * 16;
    const int nbase = ng * 32;

    // zero state (each CTA its own 16x32 region; union covers [64][1024])
    for (int o = tid; o < 512; o += 256) {
        int idx = (mbase + (o >> 5)) * DD + nbase + (o & 31);
        g_h[idx] = 0.f; g_h0[idx] = 0.f; g_hph0[idx] = 0.f;
    }
    grid_sync();

    for (int t = 0; t < TT; t++) {
        const float* wxt = g_WX + t * (BATCH*DD);
        for (int it = 0; it < 5; it++) {
            // ---- P1: F1 = elu((h+h0) @ Whid^T + bhid + wx) ----
            mm_tile<true>(g_hph0 + mbase*DD, Whid + nbase*DD, pbuf);
            __syncthreads();
            for (int o = tid; o < 512; o += 256) {
                int m = mbase + (o >> 5), n = nbase + (o & 31);
                float s = __ldg(&bhid[n]) + __ldcg(&wxt[m*DD + n]);
                #pragma unroll
                for (int w = 0; w < 8; w++) s += pbuf[w*512 + o];
                g_F1[m*DD + n] = elu_f(s);
            }
            grid_sync();

            // ---- P2: T2 = elu(F1 @ W2^T + b2) ----
            mm_tile<true>(g_F1 + mbase*DD, W2 + nbase*DD, pbuf);
            __syncthreads();
            for (int o = tid; o < 512; o += 256) {
                int m = mbase + (o >> 5), n = nbase + (o & 31);
                float s = __ldg(&b2[n]);
                #pragma unroll
                for (int w = 0; w < 8; w++) s += pbuf[w*512 + o];
                g_T2[m*DD + n] = elu_f(s);
            }
            grid_sync();

            // ---- P3: Fn = elu(T2 @ W3^T + b3); h update ----
            mm_tile<true>(g_T2 + mbase*DD, W3 + nbase*DD, pbuf);
            __syncthreads();
            {
                float eta = __ldg(&etas[it]);
                for (int o = tid; o < 512; o += 256) {
                    int m = mbase + (o >> 5), n = nbase + (o & 31);
                    float s = __ldg(&b3[n]);
                    #pragma unroll
                    for (int w = 0; w < 8; w++) s += pbuf[w*512 + o];
                    float fn   = elu_f(s);
                    int idx    = m*DD + n;
                    float hold = __ldcg(&g_h[idx]);
                    float hp   = __ldcg(&g_hph0[idx]);
                    float hnew = hold + eta * (fn - hp);
                    g_h[idx] = hnew;
                    if (it == 4) {
                        g_h0[idx]   = hnew;
                        g_hph0[idx] = 2.f * hnew;
                        g_H[(t*BATCH + m)*DD + n] = hnew;
                    } else {
                        g_hph0[idx] = hnew + __ldcg(&g_h0[idx]);
                    }
                }
            }
            grid_sync();
        }
    }
}

// ---------------- big parallel GEMMs (C = A @ W^T + bias) ----------------
__device__ __forceinline__ void gemm_body(const float* __restrict__ A,
                                          const float* __restrict__ Wm,
                                          const float* __restrict__ bias,
                                          float* __restrict__ Cout)
{
    __shared__ float pbuf[8*512];
    const int tid = threadIdx.x;
    const int mg  = blockIdx.y;   // M/16 tiles
    const int ng  = blockIdx.x;   // 32 n tiles
    mm_tile<false>(A + mg*16*DD, Wm + ng*32*DD, pbuf);
    __syncthreads();
    for (int o = tid; o < 512; o += 256) {
        int m = mg*16 + (o >> 5), n = ng*32 + (o & 31);
        float s = __ldg(&bias[n]);
        #pragma unroll
        for (int w = 0; w < 8; w++) s += pbuf[w*512 + o];
        Cout[m*DD + n] = s;
    }
}

__global__ void __launch_bounds__(256, 1) gemm_wx(const float* __restrict__ W_in,
                                                  const float* __restrict__ b_in) {
    gemm_body(g_xT, W_in, b_in, g_WX);
}
__global__ void __launch_bounds__(256, 1) gemm_out(const float* __restrict__ W_out,
                                                   const float* __restrict__ b_out) {
    gemm_body(g_H, W_out, b_out, g_Y);
}

// ---------------- transposes ----------------
// x[b][k][t] ([64][1024][200]) -> g_xT[(t*64+b)*1024 + k]
__global__ void transpose_x(const float* __restrict__ x)
{
    __shared__ float tile[32][33];
    const int b  = blockIdx.z;
    const int k0 = blockIdx.y * 32;
    const int t0 = blockIdx.x * 32;
    const int tx = threadIdx.x, ty = threadIdx.y;

    for (int kk = ty; kk < 32; kk += 8) {
        int t = t0 + tx;
        tile[kk][tx] = (t < TT) ? x[(size_t)b*DD*TT + (size_t)(k0 + kk)*TT + t] : 0.f;
    }
    __syncthreads();
    for (int tl = ty; tl < 32; tl += 8) {
        int t = t0 + tl;
        if (t < TT)
            g_xT[((size_t)t*BATCH + b)*DD + k0 + tx] = tile[tx][tl];
    }
}

// g_Y[(t*64+b)*1024 + n] -> out[b][n][t] ([64][1024][200])
__global__ void transpose_y(float* __restrict__ out)
{
    __shared__ float tile[32][33];
    const int b  = blockIdx.z;
    const int n0 = blockIdx.y * 32;
    const int t0 = blockIdx.x * 32;
    const int tx = threadIdx.x, ty = threadIdx.y;

    for (int tl = ty; tl < 32; tl += 8) {
        int t = t0 + tl;
        tile[tl][tx] = (t < TT) ? g_Y[((size_t)t*BATCH + b)*DD + n0 + tx] : 0.f;
    }
    __syncthreads();
    for (int nn = ty; nn < 32; nn += 8) {
        int t = t0 + tx;
        if (t < TT)
            out[(size_t)b*DD*TT + (size_t)(n0 + nn)*TT + t] = tile[tx][nn];
    }
}

// ---------------- launch ----------------
extern "C" void kernel_launch(void* const* d_in, const int* in_sizes, int n_in,
                              void* d_out, int out_size)
{
    (void)in_sizes; (void)n_in; (void)out_size;
    const float* x     = (const float*)d_in[0];
    const float* W_in  = (const float*)d_in[1];
    const float* b_in  = (const float*)d_in[2];
    const float* W_hid = (const float*)d_in[3];
    const float* b_hid = (const float*)d_in[4];
    const float* W2    = (const float*)d_in[5];
    const float* b2    = (const float*)d_in[6];
    const float* W3    = (const float*)d_in[7];
    const float* b3    = (const float*)d_in[8];
    const float* W_out = (const float*)d_in[9];
    const float* b_out = (const float*)d_in[10];
    const float* etas  = (const float*)d_in[11];
    float* out = (float*)d_out;

    dim3 tb(32, 8);
    dim3 tgx((TT + 31)/32, DD/32, BATCH);
    transpose_x<<<tgx, tb>>>(x);

    dim3 ggrid(DD/32, TB/16);           // (32, 800)
    gemm_wx<<<ggrid, 256>>>(W_in, b_in);

    ernn_seq<<<128, 256>>>(W_hid, b_hid, W2, b2, W3, b3, etas);

    gemm_out<<<ggrid, 256>>>(W_out, b_out);

    dim3 tgy((TT + 31)/32, DD/32, BATCH);
    transpose_y<<<tgy, tb>>>(out);
}

// round 12
// speedup vs baseline: 2.3850x; 2.3850x over previous
#include <cuda_runtime.h>
#include <cstdint>

#define DD 1024
#define BATCH 64
#define TT 200
#define TB (TT*BATCH)
#define NCTA 128
#define NPER 8
#define WSTRIDE 1028
#define ASTRIDE 132

typedef unsigned long long ull;

// ---------------- scratch (static __device__, no allocations) ----------------
__device__ float g_xT[TB*DD];     // x transposed: [t][b][k]
__device__ float g_WX[TB*DD];     // wx for all timesteps
__device__ float g_H [TB*DD];     // h_t for all timesteps
__device__ float g_Y [TB*DD];     // y before final transpose
__device__ float g_A0[BATCH*DD];  // h+h0  (GEMM input P1)
__device__ float g_A1[BATCH*DD];  // F1    (GEMM input P2)
__device__ float g_A2[BATCH*DD];  // T2    (GEMM input P3)
__device__ unsigned g_bar_count;
__device__ volatile unsigned g_bar_gen;

// ---------------- helpers ----------------
__device__ __forceinline__ void ffma2(ull& d, ull a, ull b) {
    asm("fma.rn.f32x2 %0, %1, %2, %0;" : "+l"(d) : "l"(a), "l"(b));
}
__device__ __forceinline__ float hsum2(ull v) {
    float lo, hi;
    asm("mov.b64 {%0,%1}, %2;" : "=f"(lo), "=f"(hi) : "l"(v));
    return lo + hi;
}
__device__ __forceinline__ float elu_f(float x) { return x > 0.f ? x : expm1f(x); }

__device__ __forceinline__ void grid_sync() {
    __syncthreads();
    if (threadIdx.x == 0) {
        unsigned gen = g_bar_gen;
        __threadfence();
        if (atomicAdd(&g_bar_count, 1) == gridDim.x - 1) {
            g_bar_count = 0;
            __threadfence();
            g_bar_gen = gen + 1;
        } else {
            while (g_bar_gen == gen) { __nanosleep(32); }
            __threadfence();
        }
    }
    __syncthreads();
}

// ---------------- sequential-phase GEMM core ----------------
// C[64][8] = A[64][1024] @ Wslice[8][1024]^T  for this CTA's 8-column slice.
// A staged from gmem in coalesced 64x128 chunks (double buffered).
// Warps: mh = warp&1 (m half), kq = warp>>2.. (K quarter). Thread tile 4m x 2n.
// Result: out2[e] = raw dot for output o = tid*2+e (o: m=o>>3, n=o&7).
__device__ __forceinline__ void mm_phase(const float* __restrict__ Ag,
                                         const float* __restrict__ sW,
                                         float* __restrict__ sA,
                                         float* __restrict__ red,
                                         float out2[2])
{
    const int tid  = threadIdx.x;
    const int warp = tid >> 5, lane = tid & 31;
    const int mh = warp & 1, kq = warp >> 1;
    const int mlane = lane >> 2, nlane = lane & 3;

    // stage chunk 0 (coalesced: warp covers 8 rows, lanes cover 128 k as float4)
    {
        ulonglong2 st[8];
        #pragma unroll
        for (int p = 0; p < 8; p++)
            st[p] = __ldcg((const ulonglong2*)(Ag + (p*8 + warp)*DD + lane*4));
        #pragma unroll
        for (int p = 0; p < 8; p++)
            *(ulonglong2*)&sA[(p*8 + warp)*ASTRIDE + lane*4] = st[p];
    }
    __syncthreads();

    ull acc[4][2];
    #pragma unroll
    for (int i = 0; i < 4; i++) { acc[i][0] = 0ull; acc[i][1] = 0ull; }

    #pragma unroll 1
    for (int c = 0; c < 8; c++) {
        ulonglong2 st[8];
        if (c < 7) {
            #pragma unroll
            for (int p = 0; p < 8; p++)
                st[p] = __ldcg((const ulonglong2*)(Ag + (p*8 + warp)*DD + (c+1)*128 + lane*4));
        }
        const float* sAb = sA + (c & 1) * 64 * ASTRIDE;
        const int kb = kq * 32;
        #pragma unroll
        for (int q = 0; q < 8; q++) {
            const int k0 = kb + q*4;
            ulonglong2 a[4], w[2];
            #pragma unroll
            for (int i = 0; i < 4; i++)
                a[i] = *(const ulonglong2*)&sAb[(mh*32 + i*8 + mlane)*ASTRIDE + k0];
            #pragma unroll
            for (int j = 0; j < 2; j++)
                w[j] = *(const ulonglong2*)&sW[(j*4 + nlane)*WSTRIDE + c*128 + k0];
            #pragma unroll
            for (int i = 0; i < 4; i++)
                #pragma unroll
                for (int j = 0; j < 2; j++) {
                    ffma2(acc[i][j], a[i].x, w[j].x);
                    ffma2(acc[i][j], a[i].y, w[j].y);
                }
        }
        if (c < 7) {
            float* dst = sA + ((c+1) & 1) * 64 * ASTRIDE;
            #pragma unroll
            for (int p = 0; p < 8; p++)
                *(ulonglong2*)&dst[(p*8 + warp)*ASTRIDE + lane*4] = st[p];
        }
        __syncthreads();
    }

    // cross-warp K reduction via SMEM
    #pragma unroll
    for (int i = 0; i < 4; i++)
        #pragma unroll
        for (int j = 0; j < 2; j++)
            red[(kq*2 + mh)*256 + lane*8 + i*2 + j] = hsum2(acc[i][j]);
    __syncthreads();
    #pragma unroll
    for (int e = 0; e < 2; e++) {
        const int o = tid*2 + e;
        const int m = o >> 3, n = o & 7;
        const int mh2 = m >> 5, r = m & 31, i = r >> 3, ml2 = r & 7;
        const int j = n >> 2, nl2 = n & 3;
        const int lane2 = ml2*4 + nl2;
        float s = 0.f;
        #pragma unroll
        for (int kk = 0; kk < 4; kk++)
            s += red[(kk*2 + mh2)*256 + lane2*8 + i*2 + j];
        out2[e] = s;
    }
    __syncthreads();
}

// ---------------- persistent sequential kernel ----------------
// SMEM: sW1/sW2/sW3 [8][1028] + sA[2][64][132] + red[2048] + state 3*512
#define SEQ_SMEM_FLOATS (3*NPER*WSTRIDE + 2*64*ASTRIDE + 2048 + 3*512)
#define SEQ_SMEM_BYTES  (SEQ_SMEM_FLOATS*4)

__global__ void __launch_bounds__(256, 1) ernn_seq(
    const float* __restrict__ Whid, const float* __restrict__ bhid,
    const float* __restrict__ Wm2,  const float* __restrict__ b2,
    const float* __restrict__ Wm3,  const float* __restrict__ b3,
    const float* __restrict__ etas)
{
    extern __shared__ float sm[];
    float* sW1  = sm;
    float* sW2  = sW1 + NPER*WSTRIDE;
    float* sW3  = sW2 + NPER*WSTRIDE;
    float* sA   = sW3 + NPER*WSTRIDE;
    float* red  = sA + 2*64*ASTRIDE;
    float* sh_h  = red + 2048;
    float* sh_h0 = sh_h + 512;
    float* sh_hp = sh_h0 + 512;

    const int tid   = threadIdx.x;
    const int nbase = blockIdx.x * NPER;

    // preload this CTA's 8-row weight slices (coalesced float4)
    for (int idx = tid; idx < NPER*256; idx += 256) {
        const int row = idx >> 8, q = idx & 255;
        *(float4*)&sW1[row*WSTRIDE + q*4] = __ldg((const float4*)&Whid[(nbase+row)*DD + q*4]);
        *(float4*)&sW2[row*WSTRIDE + q*4] = __ldg((const float4*)&Wm2 [(nbase+row)*DD + q*4]);
        *(float4*)&sW3[row*WSTRIDE + q*4] = __ldg((const float4*)&Wm3 [(nbase+row)*DD + q*4]);
    }
    // zero state + own columns of g_A0
    for (int o = tid; o < 512; o += 256) {
        sh_h[o] = 0.f; sh_h0[o] = 0.f; sh_hp[o] = 0.f;
        const int m = o >> 3, n = o & 7;
        g_A0[m*DD + nbase + n] = 0.f;
    }
    grid_sync();

    // per-thread output coords + biases (thread owns outputs o0, o0+1 forever)
    const int o0 = tid*2;
    const int m0 = o0 >> 3,       n0 = o0 & 7;
    const int m1 = (o0+1) >> 3,   n1 = (o0+1) & 7;
    const float bh0 = __ldg(&bhid[nbase+n0]), bh1 = __ldg(&bhid[nbase+n1]);
    const float b20 = __ldg(&b2[nbase+n0]),   b21 = __ldg(&b2[nbase+n1]);
    const float b30 = __ldg(&b3[nbase+n0]),   b31 = __ldg(&b3[nbase+n1]);
    float e5[5];
    #pragma unroll
    for (int k = 0; k < 5; k++) e5[k] = __ldg(&etas[k]);

    float out2[2];
    #pragma unroll 1
    for (int t = 0; t < TT; t++) {
        const float* wxt = g_WX + (size_t)t * BATCH * DD;
        #pragma unroll 1
        for (int it = 0; it < 5; it++) {
            // ---- P1: F1 = elu((h+h0)@Whid^T + bhid + wx) ----
            mm_phase(g_A0, sW1, sA, red, out2);
            {
                float s0 = out2[0] + bh0 + __ldg(&wxt[m0*DD + nbase + n0]);
                float s1 = out2[1] + bh1 + __ldg(&wxt[m1*DD + nbase + n1]);
                __stcg(&g_A1[m0*DD + nbase + n0], elu_f(s0));
                __stcg(&g_A1[m1*DD + nbase + n1], elu_f(s1));
            }
            grid_sync();

            // ---- P2: T2 = elu(F1@W2^T + b2) ----
            mm_phase(g_A1, sW2, sA, red, out2);
            __stcg(&g_A2[m0*DD + nbase + n0], elu_f(out2[0] + b20));
            __stcg(&g_A2[m1*DD + nbase + n1], elu_f(out2[1] + b21));
            grid_sync();

            // ---- P3: Fn = elu(T2@W3^T + b3); state update ----
            mm_phase(g_A2, sW3, sA, red, out2);
            {
                const float eta = e5[it];
                const float fn0 = elu_f(out2[0] + b30);
                const float fn1 = elu_f(out2[1] + b31);
                const float h0n = sh_h[o0]   + eta * (fn0 - sh_hp[o0]);
                const float h1n = sh_h[o0+1] + eta * (fn1 - sh_hp[o0+1]);
                sh_h[o0] = h0n; sh_h[o0+1] = h1n;
                float hp0, hp1;
                if (it == 4) {
                    sh_h0[o0] = h0n; sh_h0[o0+1] = h1n;
                    hp0 = 2.f*h0n; hp1 = 2.f*h1n;
                    g_H[((size_t)t*BATCH + m0)*DD + nbase + n0] = h0n;
                    g_H[((size_t)t*BATCH + m1)*DD + nbase + n1] = h1n;
                } else {
                    hp0 = h0n + sh_h0[o0]; hp1 = h1n + sh_h0[o0+1];
                }
                sh_hp[o0] = hp0; sh_hp[o0+1] = hp1;
                __stcg(&g_A0[m0*DD + nbase + n0], hp0);
                __stcg(&g_A0[m1*DD + nbase + n1], hp1);
            }
            grid_sync();
        }
    }
}

// ---------------- parallel tiled GEMM: C = A @ W^T + bias ----------------
// CTA tile 64m x 64n, K chunks of 128. Warps: mh(2) x nq(4); thread 4m x 4n.
#define PAR_SMEM_BYTES (2*64*ASTRIDE*4)

__global__ void __launch_bounds__(256, 1) gemm64(const float* __restrict__ A,
                                                 const float* __restrict__ Wm,
                                                 const float* __restrict__ bias,
                                                 float* __restrict__ C)
{
    extern __shared__ float sm[];
    float* sA = sm;
    float* sB = sm + 64*ASTRIDE;

    const int tid  = threadIdx.x;
    const int warp = tid >> 5, lane = tid & 31;
    const int mh = warp & 1, nq = warp >> 1;
    const int mlane = lane >> 2, nlane = lane & 3;
    const int mbase = blockIdx.y * 64, nbase = blockIdx.x * 64;

    ull acc[4][4];
    #pragma unroll
    for (int i = 0; i < 4; i++)
        #pragma unroll
        for (int j = 0; j < 4; j++) acc[i][j] = 0ull;

    #pragma unroll 1
    for (int c = 0; c < 8; c++) {
        if (c) __syncthreads();
        #pragma unroll
        for (int p = 0; p < 8; p++) {
            const int row = p*8 + warp;
            *(ulonglong2*)&sA[row*ASTRIDE + lane*4] =
                __ldg((const ulonglong2*)(A  + (size_t)(mbase+row)*DD + c*128 + lane*4));
            *(ulonglong2*)&sB[row*ASTRIDE + lane*4] =
                __ldg((const ulonglong2*)(Wm + (size_t)(nbase+row)*DD + c*128 + lane*4));
        }
        __syncthreads();
        #pragma unroll 4
        for (int q = 0; q < 32; q++) {
            const int k0 = q*4;
            ulonglong2 a[4], w[4];
            #pragma unroll
            for (int i = 0; i < 4; i++)
                a[i] = *(const ulonglong2*)&sA[(mh*32 + i*8 + mlane)*ASTRIDE + k0];
            #pragma unroll
            for (int j = 0; j < 4; j++)
                w[j] = *(const ulonglong2*)&sB[(nq*16 + j*4 + nlane)*ASTRIDE + k0];
            #pragma unroll
            for (int i = 0; i < 4; i++)
                #pragma unroll
                for (int j = 0; j < 4; j++) {
                    ffma2(acc[i][j], a[i].x, w[j].x);
                    ffma2(acc[i][j], a[i].y, w[j].y);
                }
        }
    }
    #pragma unroll
    for (int i = 0; i < 4; i++)
        #pragma unroll
        for (int j = 0; j < 4; j++) {
            const int m = mbase + mh*32 + i*8 + mlane;
            const int n = nbase + nq*16 + j*4 + nlane;
            C[(size_t)m*DD + n] = hsum2(acc[i][j]) + __ldg(&bias[n]);
        }
}

__global__ void __launch_bounds__(256,1) gemm_wx(const float* __restrict__ W_in,
                                                 const float* __restrict__ b_in);
__global__ void __launch_bounds__(256,1) gemm_out_k(const float* __restrict__ W_out,
                                                    const float* __restrict__ b_out);

// ---------------- transposes ----------------
// x[b][k][t] ([64][1024][200]) -> g_xT[(t*64+b)*1024 + k]
__global__ void transpose_x(const float* __restrict__ x)
{
    __shared__ float tile[32][33];
    const int b  = blockIdx.z;
    const int k0 = blockIdx.y * 32;
    const int t0 = blockIdx.x * 32;
    const int tx = threadIdx.x, ty = threadIdx.y;

    for (int kk = ty; kk < 32; kk += 8) {
        int t = t0 + tx;
        tile[kk][tx] = (t < TT) ? x[(size_t)b*DD*TT + (size_t)(k0 + kk)*TT + t] : 0.f;
    }
    __syncthreads();
    for (int tl = ty; tl < 32; tl += 8) {
        int t = t0 + tl;
        if (t < TT)
            g_xT[((size_t)t*BATCH + b)*DD + k0 + tx] = tile[tx][tl];
    }
}

// g_Y[(t*64+b)*1024 + n] -> out[b][n][t] ([64][1024][200])
__global__ void transpose_y(float* __restrict__ out)
{
    __shared__ float tile[32][33];
    const int b  = blockIdx.z;
    const int n0 = blockIdx.y * 32;
    const int t0 = blockIdx.x * 32;
    const int tx = threadIdx.x, ty = threadIdx.y;

    for (int tl = ty; tl < 32; tl += 8) {
        int t = t0 + tl;
        tile[tl][tx] = (t < TT) ? g_Y[((size_t)t*BATCH + b)*DD + n0 + tx] : 0.f;
    }
    __syncthreads();
    for (int nn = ty; nn < 32; nn += 8) {
        int t = t0 + tx;
        if (t < TT)
            out[(size_t)b*DD*TT + (size_t)(n0 + nn)*TT + t] = tile[tx][nn];
    }
}

// ---------------- launch ----------------
extern "C" void kernel_launch(void* const* d_in, const int* in_sizes, int n_in,
                              void* d_out, int out_size)
{
    (void)in_sizes; (void)n_in; (void)out_size;
    const float* x     = (const float*)d_in[0];
    const float* W_in  = (const float*)d_in[1];
    const float* b_in  = (const float*)d_in[2];
    const float* W_hid = (const float*)d_in[3];
    const float* b_hid = (const float*)d_in[4];
    const float* W2    = (const float*)d_in[5];
    const float* b2    = (const float*)d_in[6];
    const float* W3    = (const float*)d_in[7];
    const float* b3    = (const float*)d_in[8];
    const float* W_out = (const float*)d_in[9];
    const float* b_out = (const float*)d_in[10];
    const float* etas  = (const float*)d_in[11];
    float* out = (float*)d_out;

    cudaFuncSetAttribute(ernn_seq, cudaFuncAttributeMaxDynamicSharedMemorySize, SEQ_SMEM_BYTES);
    cudaFuncSetAttribute(gemm64,   cudaFuncAttributeMaxDynamicSharedMemorySize, PAR_SMEM_BYTES);

    dim3 tb(32, 8);
    dim3 tgx((TT + 31)/32, DD/32, BATCH);
    transpose_x<<<tgx, tb>>>(x);

    // WX = xT @ W_in^T + b_in   (M = 12800)
    {
        float* gWX; float* gxT;
        cudaGetSymbolAddress((void**)&gWX, g_WX);
        cudaGetSymbolAddress((void**)&gxT, g_xT);
        dim3 gg(DD/64, TB/64);
        gemm64<<<gg, 256, PAR_SMEM_BYTES>>>(gxT, W_in, b_in, gWX);
    }

    ernn_seq<<<NCTA, 256, SEQ_SMEM_BYTES>>>(W_hid, b_hid, W2, b2, W3, b3, etas);

    // Y = H @ W_out^T + b_out
    {
        float* gH; float* gY;
        cudaGetSymbolAddress((void**)&gH, g_H);
        cudaGetSymbolAddress((void**)&gY, g_Y);
        dim3 gg(DD/64, TB/64);
        gemm64<<<gg, 256, PAR_SMEM_BYTES>>>(gH, W_out, b_out, gY);
    }

    dim3 tgy((TT + 31)/32, DD/32, BATCH);
    transpose_y<<<tgy, tb>>>(out);
}